// round 17
// baseline (speedup 1.0000x reference)
#include <cuda_runtime.h>
#include <math.h>
#include <stdint.h>

#define CC   128
#define NPTS 4096
#define TN   32
#define NG   16
#define OPT  8
#define OP2  4
#define NTHR 512
#define EPSV 1e-12f
#define WCH  4              // k-steps per staged chunk
#define WCHF (WCH * CC)     // floats per chunk (512)

typedef unsigned long long ull;

// Pre-expanded (se3) + transposed weights: Wt[c][o] = W[o][c]
__device__ float g_W1t [CC * CC];
__device__ float g_W2t [CC * CC];
__device__ float g_W3t [2 * CC * CC];
__device__ float g_svWt[CC * CC];
__device__ float g_vsdWt[CC * CC];
__device__ float g_vsWt[CC * CC];
__device__ float g_ssWt[CC * CC];

__global__ void prep_kernel(const float* __restrict__ weight,
                            const float* __restrict__ sv_W,
                            const float* __restrict__ cross_weight,
                            const float* __restrict__ crossfc_weight,
                            const float* __restrict__ vsdir_weight,
                            const float* __restrict__ vs_W,
                            const float* __restrict__ ss_W)
{
    const int o = blockIdx.x;
    const int t = threadIdx.x;
    __shared__ float sred[128];

    float w = (t < CC - 1) ? weight[o * (CC - 1) + t] : 0.f;
    sred[t] = w; __syncthreads();
    for (int k = 64; k > 0; k >>= 1) { if (t < k) sred[t] += sred[t + k]; __syncthreads(); }
    float rs1 = sred[0]; __syncthreads();
    if (t < CC - 1) g_W1t[t * CC + o] = w;
    else            g_W1t[(CC - 1) * CC + o] = 1.f - rs1;

    float w2 = (t < CC - 1) ? cross_weight[o * (CC - 1) + t] : 0.f;
    sred[t] = w2; __syncthreads();
    for (int k = 64; k > 0; k >>= 1) { if (t < k) sred[t] += sred[t + k]; __syncthreads(); }
    float rs2 = sred[0]; __syncthreads();
    if (t < CC - 1) g_W2t[t * CC + o] = w2;
    else            g_W2t[(CC - 1) * CC + o] = 1.f - rs2;

    float a0 = crossfc_weight[o * (2 * CC - 1) + t];
    float a1 = (t < CC - 1) ? crossfc_weight[o * (2 * CC - 1) + CC + t] : 0.f;
    sred[t] = a0 + a1; __syncthreads();
    for (int k = 64; k > 0; k >>= 1) { if (t < k) sred[t] += sred[t + k]; __syncthreads(); }
    float rs3 = sred[0]; __syncthreads();
    g_W3t[t * CC + o] = a0;
    if (t < CC - 1) g_W3t[(CC + t) * CC + o] = a1;
    else            g_W3t[(2 * CC - 1) * CC + o] = 1.f - rs3;

    g_svWt [t * CC + o] = sv_W        [o * CC + t];
    g_vsdWt[t * CC + o] = vsdir_weight[o * CC + t];
    g_vsWt [t * CC + o] = vs_W        [o * CC + t];
    g_ssWt [t * CC + o] = ss_W        [o * CC + t];
}

// ---- packed f32x2 helpers ----
#define FMA2(acc, w, x) \
    asm("fma.rn.f32x2 %0, %1, %2, %3;" : "=l"(acc) : "l"(w), "l"(x), "l"(acc))
#define ADD2(d, a, b) \
    asm("add.rn.f32x2 %0, %1, %2;" : "=l"(d) : "l"(a), "l"(b))
#define PACK_DUP(out, x) \
    asm("mov.b64 %0, {%1, %1};" : "=l"(out) : "r"(__float_as_uint(x)))

__device__ __forceinline__ float lo2(ull v) { return __uint_as_float((unsigned)v); }
__device__ __forceinline__ float hi2(ull v) { return __uint_as_float((unsigned)(v >> 32)); }
__device__ __forceinline__ ull pack2(float lo, float hi) {
    return (ull)__float_as_uint(lo) | ((ull)__float_as_uint(hi) << 32);
}

// 1 / max(sqrt(x), EPSV) == rsqrt(max(x, EPSV^2))
__device__ __forceinline__ float rsq_guard(float x) {
    return rsqrtf(fmaxf(x, 1e-24f));
}

// ---- cp.async helpers ----
__device__ __forceinline__ void cpasync16(float* dst_smem, const float* src) {
    unsigned saddr = (unsigned)__cvta_generic_to_shared(dst_smem);
    asm volatile("cp.async.ca.shared.global [%0], [%1], 16;" :: "r"(saddr), "l"(src) : "memory");
}
#define CP_COMMIT() asm volatile("cp.async.commit_group;" ::: "memory")
#define CP_WAIT(n)  asm volatile("cp.async.wait_group %0;" :: "n"(n) : "memory")

// GEMM over 3-vector tile S[384][32], weights staged through smem via cp.async.
// NSL=1: each thread accumulates 8 out-channels (4 packed pairs) x 3 comps for
// ONE point (column nl). ALL 512 threads must call uniformly (has barriers).
template<bool INIT>
__device__ __forceinline__ void gemm3(const float* __restrict__ Wt,
                                      const float* __restrict__ S,
                                      float* __restrict__ wst,   // [2][WCHF]
                                      int nl, int ob, int tid,
                                      ull aX[OP2], ull aY[OP2], ull aZ[OP2])
{
    if (INIT) {
        #pragma unroll
        for (int j = 0; j < OP2; j++) { aX[j] = 0; aY[j] = 0; aZ[j] = 0; }
    }
    if (tid < 128) cpasync16(wst + 0 * WCHF + tid * 4, Wt + 0 * WCHF + tid * 4);
    CP_COMMIT();
    if (tid < 128) cpasync16(wst + 1 * WCHF + tid * 4, Wt + 1 * WCHF + tid * 4);
    CP_COMMIT();

    #pragma unroll 1
    for (int ci = 0; ci < CC / WCH; ci++) {
        if (ci == CC / WCH - 1) { CP_WAIT(0); } else { CP_WAIT(1); }
        __syncthreads();
        const float* wb = wst + (ci & 1) * WCHF + ob;
        const float* Sb = S + (size_t)(3 * ci * WCH) * TN + nl;
        #pragma unroll
        for (int r = 0; r < WCH; r++) {
            float xx = Sb[(3 * r + 0) * TN];
            float xy = Sb[(3 * r + 1) * TN];
            float xz = Sb[(3 * r + 2) * TN];
            ull x2, y2, z2;
            PACK_DUP(x2, xx); PACK_DUP(y2, xy); PACK_DUP(z2, xz);
            ull w2[OP2];
            {
                const ulonglong2* p = (const ulonglong2*)(wb + r * CC);
                ulonglong2 a = p[0], bq = p[1];   // 2x LDS.128, warp-uniform
                w2[0] = a.x; w2[1] = a.y; w2[2] = bq.x; w2[3] = bq.y;
            }
            #pragma unroll
            for (int j = 0; j < OP2; j++) {
                FMA2(aX[j], w2[j], x2);
                FMA2(aY[j], w2[j], y2);
                FMA2(aZ[j], w2[j], z2);
            }
        }
        __syncthreads();
        if (ci < CC / WCH - 2) {
            if (tid < 128) cpasync16(wst + (ci & 1) * WCHF + tid * 4,
                                     Wt + (size_t)(ci + 2) * WCHF + tid * 4);
            CP_COMMIT();
        }
    }
}

// channel (ob + jj) value from packed accumulators
#define GETA(arr, jj) ((jj & 1) ? hi2(arr[jj >> 1]) : lo2(arr[jj >> 1]))

// ---------------------------------------------------------------------------
// Fused kernel: one block = one (b, 32-point) tile. 512 threads, 2 blocks/SM.
// Each thread: 8 output channels (og 0..15) x ONE point (nl).
// ---------------------------------------------------------------------------
__global__ void __launch_bounds__(NTHR, 2)
fused_kernel(const float* __restrict__ v_in, const float* __restrict__ s_in,
             const float* __restrict__ sv_b, const float* __restrict__ vs_b,
             const float* __restrict__ ss_b, float* __restrict__ out, int B)
{
    extern __shared__ float sm[];
    float* A   = sm;                     // [384][32]  x_c, later v_cross
    float* Bm  = sm + 3 * CC * TN;       // [384][32]  s+p, later v1
    float* red = sm + 6 * CC * TN;       // [96][32]
    float* wst = red + 96 * TN;          // [2][512]   cp.async weight staging

    const int tid = threadIdx.x;
    const int nl  = tid & 31;
    const int og  = tid >> 5;            // 0..15
    const int ob  = og * OPT;

    const int b  = blockIdx.x >> 7;      // 128 tiles per batch
    const int n0 = (blockIdx.x & 127) * TN;

    // ---- load x -> A, s -> Bm[0:128] ----
    {
        const int colg = tid & 31;
        const int rq   = tid >> 5;       // 0..15
        const float* src = v_in + ((size_t)b * (3 * CC)) * NPTS + n0 + colg;
        #pragma unroll 4
        for (int it = 0; it < 24; it++) {
            int r = rq + it * 16;
            A[r * TN + colg] = src[(size_t)r * NPTS];
        }
        const float* ssrc = s_in + ((size_t)b * CC) * NPTS + n0 + colg;
        #pragma unroll 4
        for (int it = 0; it < 8; it++) {
            int r = rq + it * 16;
            Bm[r * TN + colg] = ssrc[(size_t)r * NPTS];
        }
    }
    __syncthreads();

    // ---- x channel mean; center A in place ----
    float mx, my, mz;
    {
        float px = 0, py = 0, pz = 0;
        #pragma unroll
        for (int j = 0; j < OPT; j++) {
            int c = ob + j;
            px += A[(3 * c + 0) * TN + nl];
            py += A[(3 * c + 1) * TN + nl];
            pz += A[(3 * c + 2) * TN + nl];
        }
        red[(og * 6 + 0) * TN + nl] = px;
        red[(og * 6 + 1) * TN + nl] = py;
        red[(og * 6 + 2) * TN + nl] = pz;
    }
    __syncthreads();
    mx = 0; my = 0; mz = 0;
    #pragma unroll
    for (int g = 0; g < NG; g++) {
        mx += red[(g * 6 + 0) * TN + nl];
        my += red[(g * 6 + 1) * TN + nl];
        mz += red[(g * 6 + 2) * TN + nl];
    }
    __syncthreads();
    mx *= (1.f / CC); my *= (1.f / CC); mz *= (1.f / CC);
    #pragma unroll
    for (int j = 0; j < OPT; j++) {
        int c = ob + j;
        A[(3 * c + 0) * TN + nl] -= mx;
        A[(3 * c + 1) * TN + nl] -= my;
        A[(3 * c + 2) * TN + nl] -= mz;
    }
    __syncthreads();

    ull aX[OP2], aY[OP2], aZ[OP2];

    // ================= scalar branch =================
    // dd = vsdir_weight @ x_c
    gemm3<true>(g_vsdWt, A, wst, nl, ob, tid, aX, aY, aZ);
    float tvv[OPT];
    {
        float pq = 0;
        #pragma unroll
        for (int jj = 0; jj < OPT; jj++) {
            int o = ob + jj;
            float ux = GETA(aX, jj), uy = GETA(aY, jj), uz = GETA(aZ, jj);
            float n2 = ux * ux + uy * uy + uz * uz;
            float inv = rsq_guard(n2);
            float q = (A[(3 * o + 0) * TN + nl] * ux +
                       A[(3 * o + 1) * TN + nl] * uy +
                       A[(3 * o + 2) * TN + nl] * uz) * inv;
            tvv[jj] = q;
            pq += q * q;
        }
        red[og * TN + nl] = pq;
    }
    __syncthreads();
    float Q = 0;
    #pragma unroll
    for (int g = 0; g < NG; g++) Q += red[g * TN + nl];
    __syncthreads();
    {
        float qinv = rsq_guard(Q);
        #pragma unroll
        for (int jj = 0; jj < OPT; jj++)
            Bm[(CC + ob + jj) * TN + nl] = tvv[jj] * qinv;
    }
    __syncthreads();

    // s_out = vs_W @ p + vs_b + ss_W @ s + ss_b   (direct LDG weights)
    {
        ull so2[OP2];
        #pragma unroll
        for (int j = 0; j < OP2; j++)
            so2[j] = pack2(vs_b[ob + 2 * j] + ss_b[ob + 2 * j],
                           vs_b[ob + 2 * j + 1] + ss_b[ob + 2 * j + 1]);
        #pragma unroll 4
        for (int c = 0; c < CC; c++) {
            float p = Bm[(CC + c) * TN + nl];
            float s = Bm[c * TN + nl];
            ull p2, s2;
            PACK_DUP(p2, p); PACK_DUP(s2, s);
            ull wva[OP2], wvb[OP2];
            {
                const ulonglong2* pa = (const ulonglong2*)&g_vsWt[c * CC + ob];
                ulonglong2 a = pa[0], bq = pa[1];
                wva[0] = a.x; wva[1] = a.y; wva[2] = bq.x; wva[3] = bq.y;
                const ulonglong2* pb = (const ulonglong2*)&g_ssWt[c * CC + ob];
                ulonglong2 a2 = pb[0], b2 = pb[1];
                wvb[0] = a2.x; wvb[1] = a2.y; wvb[2] = b2.x; wvb[3] = b2.y;
            }
            #pragma unroll
            for (int j = 0; j < OP2; j++) {
                FMA2(so2[j], wva[j], p2);
                FMA2(so2[j], wvb[j], s2);
            }
        }
        float* outs = out + (size_t)B * CC * 3 * NPTS + ((size_t)b * CC) * NPTS + n0 + nl;
        #pragma unroll
        for (int j = 0; j < OP2; j++) {
            outs[(size_t)(ob + 2 * j) * NPTS]     = lo2(so2[j]);
            outs[(size_t)(ob + 2 * j + 1) * NPTS] = hi2(so2[j]);
        }
    }

    // ---- t = sv_W @ s + sv_b   (direct LDG weights) ----
    ull t2[OP2];
    {
        #pragma unroll
        for (int j = 0; j < OP2; j++)
            t2[j] = pack2(sv_b[ob + 2 * j], sv_b[ob + 2 * j + 1]);
        #pragma unroll 4
        for (int c = 0; c < CC; c++) {
            float s = Bm[c * TN + nl];
            ull s2; PACK_DUP(s2, s);
            ull w2[OP2];
            {
                const ulonglong2* p = (const ulonglong2*)&g_svWt[c * CC + ob];
                ulonglong2 a = p[0], bq = p[1];
                w2[0] = a.x; w2[1] = a.y; w2[2] = bq.x; w2[3] = bq.y;
            }
            #pragma unroll
            for (int j = 0; j < OP2; j++) FMA2(t2[j], w2[j], s2);
        }
    }
    __syncthreads();

    // ================= vector branch =================
    // ---- u_c = W1 @ x_c ----
    gemm3<true>(g_W1t, A, wst, nl, ob, tid, aX, aY, aZ);
    {
        ull sx = 0, sy = 0, sz = 0, st = 0;
        #pragma unroll
        for (int j = 0; j < OP2; j++) {
            ADD2(sx, sx, aX[j]); ADD2(sy, sy, aY[j]); ADD2(sz, sz, aZ[j]);
            FMA2(st, t2[j], t2[j]);
        }
        red[(og * 6 + 0) * TN + nl] = lo2(sx) + hi2(sx);
        red[(og * 6 + 1) * TN + nl] = lo2(sy) + hi2(sy);
        red[(og * 6 + 2) * TN + nl] = lo2(sz) + hi2(sz);
        red[(og * 6 + 3) * TN + nl] = lo2(st) + hi2(st);
    }
    __syncthreads();
    float mux = 0, muy = 0, muz = 0, tss = 0;
    #pragma unroll
    for (int g = 0; g < NG; g++) {
        mux += red[(g * 6 + 0) * TN + nl];
        muy += red[(g * 6 + 1) * TN + nl];
        muz += red[(g * 6 + 2) * TN + nl];
        tss += red[(g * 6 + 3) * TN + nl];
    }
    __syncthreads();
    mux *= (1.f / CC); muy *= (1.f / CC); muz *= (1.f / CC);
    const float tinv = rsq_guard(tss);

    // v1 = (u_c - mu)*s2v + (mu + m) -> Bm; partial v1-mean
    float p1x = 0, p1y = 0, p1z = 0;
    #pragma unroll
    for (int jj = 0; jj < OPT; jj++) {
        int o = ob + jj;
        float s2v = GETA(t2, jj) * tinv;
        float ax = fmaf(GETA(aX, jj) - mux, s2v, mux + mx);
        float ay = fmaf(GETA(aY, jj) - muy, s2v, muy + my);
        float az = fmaf(GETA(aZ, jj) - muz, s2v, muz + mz);
        p1x += ax; p1y += ay; p1z += az;
        Bm[(3 * o + 0) * TN + nl] = ax;
        Bm[(3 * o + 1) * TN + nl] = ay;
        Bm[(3 * o + 2) * TN + nl] = az;
    }

    // ---- d_c = W2 @ x_c ----
    gemm3<true>(g_W2t, A, wst, nl, ob, tid, aX, aY, aZ);
    {
        ull sx = 0, sy = 0, sz = 0;
        #pragma unroll
        for (int j = 0; j < OP2; j++) {
            ADD2(sx, sx, aX[j]); ADD2(sy, sy, aY[j]); ADD2(sz, sz, aZ[j]);
        }
        red[(og * 6 + 0) * TN + nl] = lo2(sx) + hi2(sx);
        red[(og * 6 + 1) * TN + nl] = lo2(sy) + hi2(sy);
        red[(og * 6 + 2) * TN + nl] = lo2(sz) + hi2(sz);
        red[(og * 6 + 3) * TN + nl] = p1x;
        red[(og * 6 + 4) * TN + nl] = p1y;
        red[(og * 6 + 5) * TN + nl] = p1z;
    }
    __syncthreads();
    float dmx = 0, dmy = 0, dmz = 0, m1x = 0, m1y = 0, m1z = 0;
    #pragma unroll
    for (int g = 0; g < NG; g++) {
        dmx += red[(g * 6 + 0) * TN + nl]; dmy += red[(g * 6 + 1) * TN + nl];
        dmz += red[(g * 6 + 2) * TN + nl]; m1x += red[(g * 6 + 3) * TN + nl];
        m1y += red[(g * 6 + 4) * TN + nl]; m1z += red[(g * 6 + 5) * TN + nl];
    }
    __syncthreads();
    dmx *= (1.f / CC); dmy *= (1.f / CC); dmz *= (1.f / CC);
    m1x *= (1.f / CC); m1y *= (1.f / CC); m1z *= (1.f / CC);

    // ---- center d; per-channel n2; sumsq over channels ----
    ull nn2[OP2];
    {
        ull ndx, ndy, ndz;
        PACK_DUP(ndx, -dmx); PACK_DUP(ndy, -dmy); PACK_DUP(ndz, -dmz);
        ull plsum = 0;
        #pragma unroll
        for (int j = 0; j < OP2; j++) {
            ADD2(aX[j], aX[j], ndx);
            ADD2(aY[j], aY[j], ndy);
            ADD2(aZ[j], aZ[j], ndz);
            ull n2 = 0;
            FMA2(n2, aX[j], aX[j]);
            FMA2(n2, aY[j], aY[j]);
            FMA2(n2, aZ[j], aZ[j]);
            nn2[j] = n2;
            ADD2(plsum, plsum, n2);
        }
        red[og * TN + nl] = lo2(plsum) + hi2(plsum);
    }
    __syncthreads();
    float L = 0;
    #pragma unroll
    for (int g = 0; g < NG; g++) L += red[g * TN + nl];
    __syncthreads();
    const float linv = rsq_guard(L);

    // ---- v_cross = cross(ceq, v1 - v1m) + v1 -> A ----
    #pragma unroll
    for (int jj = 0; jj < OPT; jj++) {
        int o = ob + jj;
        float n2 = GETA(nn2, jj);
        float nyv = sqrtf(n2);
        float cf = linv * fminf(nyv * (1.f / EPSV), 1.f);
        float ex = GETA(aX, jj) * cf;
        float ey = GETA(aY, jj) * cf;
        float ez = GETA(aZ, jj) * cf;
        float ax = Bm[(3 * o + 0) * TN + nl];
        float ay = Bm[(3 * o + 1) * TN + nl];
        float az = Bm[(3 * o + 2) * TN + nl];
        float wx = ax - m1x, wy = ay - m1y, wz = az - m1z;
        A[(3 * o + 0) * TN + nl] = ey * wz - ez * wy + ax;
        A[(3 * o + 1) * TN + nl] = ez * wx - ex * wz + ay;
        A[(3 * o + 2) * TN + nl] = ex * wy - ey * wx + az;
    }
    __syncthreads();

    // ---- v_out = W3[:, :128] @ v_cross (A) + W3[:, 128:] @ v1 (Bm) ----
    gemm3<true >(g_W3t,           A,  wst, nl, ob, tid, aX, aY, aZ);
    gemm3<false>(g_W3t + CC * CC, Bm, wst, nl, ob, tid, aX, aY, aZ);
    {
        float* outv = out + ((size_t)b * CC) * 3 * NPTS + n0 + nl;
        #pragma unroll
        for (int j = 0; j < OP2; j++) {
            int o0 = ob + 2 * j, o1 = o0 + 1;
            outv[(size_t)(3 * o0 + 0) * NPTS] = lo2(aX[j]);
            outv[(size_t)(3 * o0 + 1) * NPTS] = lo2(aY[j]);
            outv[(size_t)(3 * o0 + 2) * NPTS] = lo2(aZ[j]);
            outv[(size_t)(3 * o1 + 0) * NPTS] = hi2(aX[j]);
            outv[(size_t)(3 * o1 + 1) * NPTS] = hi2(aY[j]);
            outv[(size_t)(3 * o1 + 2) * NPTS] = hi2(aZ[j]);
        }
    }
}

extern "C" void kernel_launch(void* const* d_in, const int* in_sizes, int n_in,
                              void* d_out, int out_size)
{
    const float* v_in      = (const float*)d_in[0];
    const float* s_in      = (const float*)d_in[1];
    const float* weight    = (const float*)d_in[2];
    const float* sv_W      = (const float*)d_in[3];
    const float* sv_b      = (const float*)d_in[4];
    const float* cross_w   = (const float*)d_in[5];
    const float* crossfc_w = (const float*)d_in[6];
    const float* vsdir_w   = (const float*)d_in[7];
    const float* vs_W      = (const float*)d_in[8];
    const float* vs_b      = (const float*)d_in[9];
    const float* ss_W      = (const float*)d_in[10];
    const float* ss_b      = (const float*)d_in[11];
    float* out = (float*)d_out;

    const int B = in_sizes[0] / (CC * 3 * NPTS);   // 16

    prep_kernel<<<CC, CC>>>(weight, sv_W, cross_w, crossfc_w, vsdir_w, vs_W, ss_W);

    // smem/block: 2 tiles (48KB each) + red 12KB + staging 4KB = 114,688 B
    // -> 2 blocks/SM = 32 warps, two desynchronized instruction streams.
    const size_t smem = (size_t)(6 * CC * TN + 96 * TN + 2 * WCHF) * sizeof(float);
    cudaFuncSetAttribute(fused_kernel, cudaFuncAttributeMaxDynamicSharedMemorySize, (int)smem);
    fused_kernel<<<B * (NPTS / TN), NTHR, smem>>>(v_in, s_in, sv_b, vs_b, ss_b, out, B);
}